// round 13
// baseline (speedup 1.0000x reference)
#include <cuda_runtime.h>
#include <cstdint>

// LightGCN 2-hop smoothing, pull-based SpMM over an on-the-fly CSR.
// fp32. Weight-folded adjacency (int2 {src, dis[src]}) kills the dependent
// dis gather; row gathers are half-warp-uniform predicated (no padded waste).
// out = (2*x0 + 2*x1 + x2)/3, x1 = S x0, x2 = S x1, S = D^-1/2 A D^-1/2.

#define EMB 64
#define MAX_NODES 200000
#define MAX_DEDGES 2500000
#define SCAN_B 256
#define MAX_SCAN_BLOCKS 1024

#define FULLMASK 0xffffffffu

__device__ int   g_deg[MAX_NODES];
__device__ float g_dis[MAX_NODES];
__device__ int   g_row[MAX_NODES + 1];
__device__ int   g_cursor[MAX_NODES];
__device__ int   g_bsums[MAX_SCAN_BLOCKS];
__device__ int2  g_adjw[MAX_DEDGES];          // {src index, dis[src] bits}
__device__ float g_x1[(size_t)MAX_NODES * EMB];

__global__ void zero_deg_kernel(int N) {
    int n = blockIdx.x * blockDim.x + threadIdx.x;
    if (n < N) g_deg[n] = 0;
}

__global__ void deg_kernel(const int* __restrict__ u_idx,
                           const int* __restrict__ i_idx,
                           int E, int NU) {
    int e4 = blockIdx.x * blockDim.x + threadIdx.x;
    int base = e4 * 4;
    if (base + 3 < E) {
        int4 u = ((const int4*)u_idx)[e4];
        int4 i = ((const int4*)i_idx)[e4];
        atomicAdd(&g_deg[u.x], 1);
        atomicAdd(&g_deg[u.y], 1);
        atomicAdd(&g_deg[u.z], 1);
        atomicAdd(&g_deg[u.w], 1);
        atomicAdd(&g_deg[NU + i.x], 1);
        atomicAdd(&g_deg[NU + i.y], 1);
        atomicAdd(&g_deg[NU + i.z], 1);
        atomicAdd(&g_deg[NU + i.w], 1);
    } else {
        for (int e = base; e < E; e++) {
            atomicAdd(&g_deg[u_idx[e]], 1);
            atomicAdd(&g_deg[NU + i_idx[e]], 1);
        }
    }
}

__global__ void scan1_kernel(int N) {
    __shared__ int warp_tot[SCAN_B / 32];
    int t = threadIdx.x;
    int lane = t & 31;
    int wid = t >> 5;
    int idx = blockIdx.x * SCAN_B + t;
    int v = (idx < N) ? g_deg[idx] : 0;
    if (idx < N) g_dis[idx] = (v > 0) ? rsqrtf((float)v) : 0.0f;

    int s = v;
    #pragma unroll
    for (int off = 1; off < 32; off <<= 1) {
        int n = __shfl_up_sync(FULLMASK, s, off);
        if (lane >= off) s += n;
    }
    if (lane == 31) warp_tot[wid] = s;
    __syncthreads();
    if (wid == 0) {
        int w = (lane < SCAN_B / 32) ? warp_tot[lane] : 0;
        #pragma unroll
        for (int off = 1; off < 32; off <<= 1) {
            int n = __shfl_up_sync(FULLMASK, w, off);
            if (lane >= off) w += n;
        }
        if (lane < SCAN_B / 32) warp_tot[lane] = w;
    }
    __syncthreads();
    int base = (wid > 0) ? warp_tot[wid - 1] : 0;
    int incl = base + s;
    if (idx < N) g_row[idx] = incl - v;
    if (t == SCAN_B - 1) g_bsums[blockIdx.x] = incl;
}

__global__ void scan_apply_kernel(int N, int twoE) {
    __shared__ int red[SCAN_B / 32];
    int t = threadIdx.x;
    int lane = t & 31;
    int wid = t >> 5;

    int sum = 0;
    for (int j = t; j < blockIdx.x; j += SCAN_B) sum += g_bsums[j];
    #pragma unroll
    for (int off = 16; off > 0; off >>= 1)
        sum += __shfl_xor_sync(FULLMASK, sum, off);
    if (lane == 0) red[wid] = sum;
    __syncthreads();
    if (wid == 0) {
        int w = (lane < SCAN_B / 32) ? red[lane] : 0;
        #pragma unroll
        for (int off = 16; off > 0; off >>= 1)
            w += __shfl_xor_sync(FULLMASK, w, off);
        if (lane == 0) red[0] = w;
    }
    __syncthreads();
    int offset = red[0];

    int idx = blockIdx.x * SCAN_B + t;
    if (idx < N) {
        int r = g_row[idx] + offset;
        g_row[idx] = r;
        g_cursor[idx] = r;
    }
    if (idx == 0) g_row[N] = twoE;
}

// Writes weight-folded adjacency: g_adjw[pos] = {src, dis[src]}.
__global__ void fill_kernel(const int* __restrict__ u_idx,
                            const int* __restrict__ i_idx,
                            int E, int NU) {
    int e = blockIdx.x * blockDim.x + threadIdx.x;
    if (e < E) {
        int u = u_idx[e];
        int g = NU + i_idx[e];
        float wu = g_dis[u];
        float wg = g_dis[g];
        int pg = atomicAdd(&g_cursor[g], 1);
        int pu = atomicAdd(&g_cursor[u], 1);
        g_adjw[pg] = make_int2(u, __float_as_int(wu));
        g_adjw[pu] = make_int2(g, __float_as_int(wg));
    }
}

// ---- pull pass 1: x1 = S x0 ----
// Warp per node. Half-warps take alternate slots; 8 slots/step; adjw gives
// {src, w} in one coalesced 8B load; row gathers predicated (uniform per
// half-warp) so padded slots issue no memory.
__global__ void pull1_kernel(const float* __restrict__ u_emb,
                             const float* __restrict__ i_emb,
                             int N, int NU) {
    int warp = (int)(((size_t)blockIdx.x * blockDim.x + threadIdx.x) >> 5);
    int lane = threadIdx.x & 31;
    if (warp >= N) return;

    int half = lane >> 4;
    int q    = lane & 15;

    int start = g_row[warp];
    int end   = g_row[warp + 1];

    float4 acc = make_float4(0.f, 0.f, 0.f, 0.f);

    for (int k = start; k < end; k += 8) {
        int i0 = k + half, i1 = k + 2 + half, i2 = k + 4 + half, i3 = k + 6 + half;
        int lim = end - 1;
        int2 a0 = g_adjw[min(i0, lim)];
        int2 a1 = g_adjw[min(i1, lim)];
        int2 a2 = g_adjw[min(i2, lim)];
        int2 a3 = g_adjw[min(i3, lim)];
        int s0 = a0.x, s1 = a1.x, s2 = a2.x, s3 = a3.x;
        float w0 = (i0 < end) ? __int_as_float(a0.y) : 0.f;
        float w1 = (i1 < end) ? __int_as_float(a1.y) : 0.f;
        float w2 = (i2 < end) ? __int_as_float(a2.y) : 0.f;
        float w3 = (i3 < end) ? __int_as_float(a3.y) : 0.f;

        float4 v0 = make_float4(0.f, 0.f, 0.f, 0.f);
        float4 v1 = v0, v2 = v0, v3 = v0;
        if (i0 < end) {
            const float4* p = (s0 < NU) ? (const float4*)(u_emb + (size_t)s0 * EMB)
                                        : (const float4*)(i_emb + (size_t)(s0 - NU) * EMB);
            v0 = p[q];
        }
        if (i1 < end) {
            const float4* p = (s1 < NU) ? (const float4*)(u_emb + (size_t)s1 * EMB)
                                        : (const float4*)(i_emb + (size_t)(s1 - NU) * EMB);
            v1 = p[q];
        }
        if (i2 < end) {
            const float4* p = (s2 < NU) ? (const float4*)(u_emb + (size_t)s2 * EMB)
                                        : (const float4*)(i_emb + (size_t)(s2 - NU) * EMB);
            v2 = p[q];
        }
        if (i3 < end) {
            const float4* p = (s3 < NU) ? (const float4*)(u_emb + (size_t)s3 * EMB)
                                        : (const float4*)(i_emb + (size_t)(s3 - NU) * EMB);
            v3 = p[q];
        }

        acc.x += w0 * v0.x + w1 * v1.x + w2 * v2.x + w3 * v3.x;
        acc.y += w0 * v0.y + w1 * v1.y + w2 * v2.y + w3 * v3.y;
        acc.z += w0 * v0.z + w1 * v1.z + w2 * v2.z + w3 * v3.z;
        acc.w += w0 * v0.w + w1 * v1.w + w2 * v2.w + w3 * v3.w;
    }

    acc.x += __shfl_xor_sync(FULLMASK, acc.x, 16);
    acc.y += __shfl_xor_sync(FULLMASK, acc.y, 16);
    acc.z += __shfl_xor_sync(FULLMASK, acc.z, 16);
    acc.w += __shfl_xor_sync(FULLMASK, acc.w, 16);

    if (half == 0) {
        float dn = g_dis[warp];
        ((float4*)(g_x1 + (size_t)warp * EMB))[q] =
            make_float4(dn * acc.x, dn * acc.y, dn * acc.z, dn * acc.w);
    }
}

// ---- pull pass 2 fused with output combine ----
// out[n] = (2*x0[n] + 2*x1[n] + dis[n]*sum dis[s]*x1[s]) / 3
__global__ void pull2_kernel(const float* __restrict__ u_emb,
                             const float* __restrict__ i_emb,
                             float* __restrict__ out,
                             int N, int NU) {
    int warp = (int)(((size_t)blockIdx.x * blockDim.x + threadIdx.x) >> 5);
    int lane = threadIdx.x & 31;
    if (warp >= N) return;

    int half = lane >> 4;
    int q    = lane & 15;

    int start = g_row[warp];
    int end   = g_row[warp + 1];

    float4 acc = make_float4(0.f, 0.f, 0.f, 0.f);

    for (int k = start; k < end; k += 8) {
        int i0 = k + half, i1 = k + 2 + half, i2 = k + 4 + half, i3 = k + 6 + half;
        int lim = end - 1;
        int2 a0 = g_adjw[min(i0, lim)];
        int2 a1 = g_adjw[min(i1, lim)];
        int2 a2 = g_adjw[min(i2, lim)];
        int2 a3 = g_adjw[min(i3, lim)];
        int s0 = a0.x, s1 = a1.x, s2 = a2.x, s3 = a3.x;
        float w0 = (i0 < end) ? __int_as_float(a0.y) : 0.f;
        float w1 = (i1 < end) ? __int_as_float(a1.y) : 0.f;
        float w2 = (i2 < end) ? __int_as_float(a2.y) : 0.f;
        float w3 = (i3 < end) ? __int_as_float(a3.y) : 0.f;

        float4 v0 = make_float4(0.f, 0.f, 0.f, 0.f);
        float4 v1 = v0, v2 = v0, v3 = v0;
        if (i0 < end) v0 = ((const float4*)(g_x1 + (size_t)s0 * EMB))[q];
        if (i1 < end) v1 = ((const float4*)(g_x1 + (size_t)s1 * EMB))[q];
        if (i2 < end) v2 = ((const float4*)(g_x1 + (size_t)s2 * EMB))[q];
        if (i3 < end) v3 = ((const float4*)(g_x1 + (size_t)s3 * EMB))[q];

        acc.x += w0 * v0.x + w1 * v1.x + w2 * v2.x + w3 * v3.x;
        acc.y += w0 * v0.y + w1 * v1.y + w2 * v2.y + w3 * v3.y;
        acc.z += w0 * v0.z + w1 * v1.z + w2 * v2.z + w3 * v3.z;
        acc.w += w0 * v0.w + w1 * v1.w + w2 * v2.w + w3 * v3.w;
    }

    acc.x += __shfl_xor_sync(FULLMASK, acc.x, 16);
    acc.y += __shfl_xor_sync(FULLMASK, acc.y, 16);
    acc.z += __shfl_xor_sync(FULLMASK, acc.z, 16);
    acc.w += __shfl_xor_sync(FULLMASK, acc.w, 16);

    if (half == 0) {
        float dn = g_dis[warp];
        const float4* x0b = (warp < NU)
            ? (const float4*)(u_emb + (size_t)warp * EMB)
            : (const float4*)(i_emb + (size_t)(warp - NU) * EMB);
        float4 x0v = x0b[q];
        float4 x1v = ((const float4*)(g_x1 + (size_t)warp * EMB))[q];
        const float inv3 = 1.0f / 3.0f;
        float4 o;
        o.x = (2.0f * x0v.x + 2.0f * x1v.x + dn * acc.x) * inv3;
        o.y = (2.0f * x0v.y + 2.0f * x1v.y + dn * acc.y) * inv3;
        o.z = (2.0f * x0v.z + 2.0f * x1v.z + dn * acc.z) * inv3;
        o.w = (2.0f * x0v.w + 2.0f * x1v.w + dn * acc.w) * inv3;
        ((float4*)(out + (size_t)warp * EMB))[q] = o;
    }
}

extern "C" void kernel_launch(void* const* d_in, const int* in_sizes, int n_in,
                              void* d_out, int out_size) {
    const float* u_emb = (const float*)d_in[0];
    const float* i_emb = (const float*)d_in[1];
    const int*   u_idx = (const int*)d_in[2];
    const int*   i_idx = (const int*)d_in[3];
    float*       out   = (float*)d_out;

    int NU = in_sizes[0] / EMB;
    int NI = in_sizes[1] / EMB;
    int E  = in_sizes[2];
    int N  = NU + NI;

    int nScanBlocks = (N + SCAN_B - 1) / SCAN_B;
    int nEdge4 = (E + 3) / 4;

    zero_deg_kernel<<<(N + 255) / 256, 256>>>(N);
    deg_kernel<<<(nEdge4 + 255) / 256, 256>>>(u_idx, i_idx, E, NU);

    scan1_kernel<<<nScanBlocks, SCAN_B>>>(N);
    scan_apply_kernel<<<nScanBlocks, SCAN_B>>>(N, 2 * E);

    fill_kernel<<<(E + 255) / 256, 256>>>(u_idx, i_idx, E, NU);

    {
        size_t threads_total = (size_t)N * 32;
        int blocks = (int)((threads_total + 255) / 256);
        pull1_kernel<<<blocks, 256>>>(u_emb, i_emb, N, NU);
        pull2_kernel<<<blocks, 256>>>(u_emb, i_emb, out, N, NU);
    }
}

// round 14
// speedup vs baseline: 1.0498x; 1.0498x over previous
#include <cuda_runtime.h>
#include <cstdint>

// LightGCN 2-hop smoothing, pull-based SpMM over an on-the-fly CSR.
// fp32. Weight-folded adjacency (int2 {src, dis[src]}) removes the dependent
// dis gather; loop is R8's branch-free clamped form (no BSSY/BSYNC regions).
// out = (2*x0 + 2*x1 + x2)/3, x1 = S x0, x2 = S x1, S = D^-1/2 A D^-1/2.

#define EMB 64
#define MAX_NODES 200000
#define MAX_DEDGES 2500000
#define SCAN_B 256
#define MAX_SCAN_BLOCKS 1024

#define FULLMASK 0xffffffffu

__device__ int   g_deg[MAX_NODES];
__device__ float g_dis[MAX_NODES];
__device__ int   g_row[MAX_NODES + 1];
__device__ int   g_cursor[MAX_NODES];
__device__ int   g_bsums[MAX_SCAN_BLOCKS];
__device__ int2  g_adjw[MAX_DEDGES];          // {src index, dis[src] bits}
__device__ float g_x1[(size_t)MAX_NODES * EMB];

__global__ void zero_deg_kernel(int N) {
    int n = blockIdx.x * blockDim.x + threadIdx.x;
    if (n < N) g_deg[n] = 0;
}

__global__ void deg_kernel(const int* __restrict__ u_idx,
                           const int* __restrict__ i_idx,
                           int E, int NU) {
    int e4 = blockIdx.x * blockDim.x + threadIdx.x;
    int base = e4 * 4;
    if (base + 3 < E) {
        int4 u = ((const int4*)u_idx)[e4];
        int4 i = ((const int4*)i_idx)[e4];
        atomicAdd(&g_deg[u.x], 1);
        atomicAdd(&g_deg[u.y], 1);
        atomicAdd(&g_deg[u.z], 1);
        atomicAdd(&g_deg[u.w], 1);
        atomicAdd(&g_deg[NU + i.x], 1);
        atomicAdd(&g_deg[NU + i.y], 1);
        atomicAdd(&g_deg[NU + i.z], 1);
        atomicAdd(&g_deg[NU + i.w], 1);
    } else {
        for (int e = base; e < E; e++) {
            atomicAdd(&g_deg[u_idx[e]], 1);
            atomicAdd(&g_deg[NU + i_idx[e]], 1);
        }
    }
}

__global__ void scan1_kernel(int N) {
    __shared__ int warp_tot[SCAN_B / 32];
    int t = threadIdx.x;
    int lane = t & 31;
    int wid = t >> 5;
    int idx = blockIdx.x * SCAN_B + t;
    int v = (idx < N) ? g_deg[idx] : 0;
    if (idx < N) g_dis[idx] = (v > 0) ? rsqrtf((float)v) : 0.0f;

    int s = v;
    #pragma unroll
    for (int off = 1; off < 32; off <<= 1) {
        int n = __shfl_up_sync(FULLMASK, s, off);
        if (lane >= off) s += n;
    }
    if (lane == 31) warp_tot[wid] = s;
    __syncthreads();
    if (wid == 0) {
        int w = (lane < SCAN_B / 32) ? warp_tot[lane] : 0;
        #pragma unroll
        for (int off = 1; off < 32; off <<= 1) {
            int n = __shfl_up_sync(FULLMASK, w, off);
            if (lane >= off) w += n;
        }
        if (lane < SCAN_B / 32) warp_tot[lane] = w;
    }
    __syncthreads();
    int base = (wid > 0) ? warp_tot[wid - 1] : 0;
    int incl = base + s;
    if (idx < N) g_row[idx] = incl - v;
    if (t == SCAN_B - 1) g_bsums[blockIdx.x] = incl;
}

__global__ void scan_apply_kernel(int N, int twoE) {
    __shared__ int red[SCAN_B / 32];
    int t = threadIdx.x;
    int lane = t & 31;
    int wid = t >> 5;

    int sum = 0;
    for (int j = t; j < blockIdx.x; j += SCAN_B) sum += g_bsums[j];
    #pragma unroll
    for (int off = 16; off > 0; off >>= 1)
        sum += __shfl_xor_sync(FULLMASK, sum, off);
    if (lane == 0) red[wid] = sum;
    __syncthreads();
    if (wid == 0) {
        int w = (lane < SCAN_B / 32) ? red[lane] : 0;
        #pragma unroll
        for (int off = 16; off > 0; off >>= 1)
            w += __shfl_xor_sync(FULLMASK, w, off);
        if (lane == 0) red[0] = w;
    }
    __syncthreads();
    int offset = red[0];

    int idx = blockIdx.x * SCAN_B + t;
    if (idx < N) {
        int r = g_row[idx] + offset;
        g_row[idx] = r;
        g_cursor[idx] = r;
    }
    if (idx == 0) g_row[N] = twoE;
}

// Writes weight-folded adjacency: g_adjw[pos] = {src, dis[src]}. 2 edges/thread.
__global__ void fill_kernel(const int* __restrict__ u_idx,
                            const int* __restrict__ i_idx,
                            int E, int NU) {
    int e2 = blockIdx.x * blockDim.x + threadIdx.x;
    int base = e2 * 2;
    if (base + 1 < E) {
        int2 u = ((const int2*)u_idx)[e2];
        int2 i = ((const int2*)i_idx)[e2];
        int gx = NU + i.x, gy = NU + i.y;
        float wux = g_dis[u.x], wuy = g_dis[u.y];
        float wgx = g_dis[gx],  wgy = g_dis[gy];
        g_adjw[atomicAdd(&g_cursor[gx], 1)]  = make_int2(u.x, __float_as_int(wux));
        g_adjw[atomicAdd(&g_cursor[gy], 1)]  = make_int2(u.y, __float_as_int(wuy));
        g_adjw[atomicAdd(&g_cursor[u.x], 1)] = make_int2(gx, __float_as_int(wgx));
        g_adjw[atomicAdd(&g_cursor[u.y], 1)] = make_int2(gy, __float_as_int(wgy));
    } else if (base < E) {
        int u = u_idx[base];
        int g = NU + i_idx[base];
        float wu = g_dis[u];
        float wg = g_dis[g];
        g_adjw[atomicAdd(&g_cursor[g], 1)] = make_int2(u, __float_as_int(wu));
        g_adjw[atomicAdd(&g_cursor[u], 1)] = make_int2(g, __float_as_int(wg));
    }
}

// ---- pull pass 1: x1 = S x0 ----
// Warp per node. Half-warps take alternate slots; 8 slots/step; clamped
// indices, loads always issued, OOB weights zeroed via select (branch-free).
__global__ void pull1_kernel(const float* __restrict__ u_emb,
                             const float* __restrict__ i_emb,
                             int N, int NU) {
    int warp = (int)(((size_t)blockIdx.x * blockDim.x + threadIdx.x) >> 5);
    int lane = threadIdx.x & 31;
    if (warp >= N) return;

    int half = lane >> 4;
    int q    = lane & 15;

    int start = g_row[warp];
    int end   = g_row[warp + 1];

    float4 acc = make_float4(0.f, 0.f, 0.f, 0.f);

    for (int k = start; k < end; k += 8) {
        int i0 = k + half, i1 = k + 2 + half, i2 = k + 4 + half, i3 = k + 6 + half;
        int lim = end - 1;
        int2 a0 = g_adjw[min(i0, lim)];
        int2 a1 = g_adjw[min(i1, lim)];
        int2 a2 = g_adjw[min(i2, lim)];
        int2 a3 = g_adjw[min(i3, lim)];
        int s0 = a0.x, s1 = a1.x, s2 = a2.x, s3 = a3.x;
        float w0 = (i0 < end) ? __int_as_float(a0.y) : 0.f;
        float w1 = (i1 < end) ? __int_as_float(a1.y) : 0.f;
        float w2 = (i2 < end) ? __int_as_float(a2.y) : 0.f;
        float w3 = (i3 < end) ? __int_as_float(a3.y) : 0.f;
        const float4* p0 = (s0 < NU) ? (const float4*)(u_emb + (size_t)s0 * EMB)
                                     : (const float4*)(i_emb + (size_t)(s0 - NU) * EMB);
        const float4* p1 = (s1 < NU) ? (const float4*)(u_emb + (size_t)s1 * EMB)
                                     : (const float4*)(i_emb + (size_t)(s1 - NU) * EMB);
        const float4* p2 = (s2 < NU) ? (const float4*)(u_emb + (size_t)s2 * EMB)
                                     : (const float4*)(i_emb + (size_t)(s2 - NU) * EMB);
        const float4* p3 = (s3 < NU) ? (const float4*)(u_emb + (size_t)s3 * EMB)
                                     : (const float4*)(i_emb + (size_t)(s3 - NU) * EMB);
        float4 v0 = p0[q], v1 = p1[q], v2 = p2[q], v3 = p3[q];
        acc.x += w0 * v0.x + w1 * v1.x + w2 * v2.x + w3 * v3.x;
        acc.y += w0 * v0.y + w1 * v1.y + w2 * v2.y + w3 * v3.y;
        acc.z += w0 * v0.z + w1 * v1.z + w2 * v2.z + w3 * v3.z;
        acc.w += w0 * v0.w + w1 * v1.w + w2 * v2.w + w3 * v3.w;
    }

    acc.x += __shfl_xor_sync(FULLMASK, acc.x, 16);
    acc.y += __shfl_xor_sync(FULLMASK, acc.y, 16);
    acc.z += __shfl_xor_sync(FULLMASK, acc.z, 16);
    acc.w += __shfl_xor_sync(FULLMASK, acc.w, 16);

    if (half == 0) {
        float dn = g_dis[warp];
        ((float4*)(g_x1 + (size_t)warp * EMB))[q] =
            make_float4(dn * acc.x, dn * acc.y, dn * acc.z, dn * acc.w);
    }
}

// ---- pull pass 2 fused with output combine ----
// out[n] = (2*x0[n] + 2*x1[n] + dis[n]*sum dis[s]*x1[s]) / 3
__global__ void pull2_kernel(const float* __restrict__ u_emb,
                             const float* __restrict__ i_emb,
                             float* __restrict__ out,
                             int N, int NU) {
    int warp = (int)(((size_t)blockIdx.x * blockDim.x + threadIdx.x) >> 5);
    int lane = threadIdx.x & 31;
    if (warp >= N) return;

    int half = lane >> 4;
    int q    = lane & 15;

    int start = g_row[warp];
    int end   = g_row[warp + 1];

    float4 acc = make_float4(0.f, 0.f, 0.f, 0.f);

    for (int k = start; k < end; k += 8) {
        int i0 = k + half, i1 = k + 2 + half, i2 = k + 4 + half, i3 = k + 6 + half;
        int lim = end - 1;
        int2 a0 = g_adjw[min(i0, lim)];
        int2 a1 = g_adjw[min(i1, lim)];
        int2 a2 = g_adjw[min(i2, lim)];
        int2 a3 = g_adjw[min(i3, lim)];
        int s0 = a0.x, s1 = a1.x, s2 = a2.x, s3 = a3.x;
        float w0 = (i0 < end) ? __int_as_float(a0.y) : 0.f;
        float w1 = (i1 < end) ? __int_as_float(a1.y) : 0.f;
        float w2 = (i2 < end) ? __int_as_float(a2.y) : 0.f;
        float w3 = (i3 < end) ? __int_as_float(a3.y) : 0.f;
        float4 v0 = ((const float4*)(g_x1 + (size_t)s0 * EMB))[q];
        float4 v1 = ((const float4*)(g_x1 + (size_t)s1 * EMB))[q];
        float4 v2 = ((const float4*)(g_x1 + (size_t)s2 * EMB))[q];
        float4 v3 = ((const float4*)(g_x1 + (size_t)s3 * EMB))[q];
        acc.x += w0 * v0.x + w1 * v1.x + w2 * v2.x + w3 * v3.x;
        acc.y += w0 * v0.y + w1 * v1.y + w2 * v2.y + w3 * v3.y;
        acc.z += w0 * v0.z + w1 * v1.z + w2 * v2.z + w3 * v3.z;
        acc.w += w0 * v0.w + w1 * v1.w + w2 * v2.w + w3 * v3.w;
    }

    acc.x += __shfl_xor_sync(FULLMASK, acc.x, 16);
    acc.y += __shfl_xor_sync(FULLMASK, acc.y, 16);
    acc.z += __shfl_xor_sync(FULLMASK, acc.z, 16);
    acc.w += __shfl_xor_sync(FULLMASK, acc.w, 16);

    if (half == 0) {
        float dn = g_dis[warp];
        const float4* x0b = (warp < NU)
            ? (const float4*)(u_emb + (size_t)warp * EMB)
            : (const float4*)(i_emb + (size_t)(warp - NU) * EMB);
        float4 x0v = x0b[q];
        float4 x1v = ((const float4*)(g_x1 + (size_t)warp * EMB))[q];
        const float inv3 = 1.0f / 3.0f;
        float4 o;
        o.x = (2.0f * x0v.x + 2.0f * x1v.x + dn * acc.x) * inv3;
        o.y = (2.0f * x0v.y + 2.0f * x1v.y + dn * acc.y) * inv3;
        o.z = (2.0f * x0v.z + 2.0f * x1v.z + dn * acc.z) * inv3;
        o.w = (2.0f * x0v.w + 2.0f * x1v.w + dn * acc.w) * inv3;
        ((float4*)(out + (size_t)warp * EMB))[q] = o;
    }
}

extern "C" void kernel_launch(void* const* d_in, const int* in_sizes, int n_in,
                              void* d_out, int out_size) {
    const float* u_emb = (const float*)d_in[0];
    const float* i_emb = (const float*)d_in[1];
    const int*   u_idx = (const int*)d_in[2];
    const int*   i_idx = (const int*)d_in[3];
    float*       out   = (float*)d_out;

    int NU = in_sizes[0] / EMB;
    int NI = in_sizes[1] / EMB;
    int E  = in_sizes[2];
    int N  = NU + NI;

    int nScanBlocks = (N + SCAN_B - 1) / SCAN_B;
    int nEdge4 = (E + 3) / 4;
    int nEdge2 = (E + 1) / 2;

    zero_deg_kernel<<<(N + 255) / 256, 256>>>(N);
    deg_kernel<<<(nEdge4 + 255) / 256, 256>>>(u_idx, i_idx, E, NU);

    scan1_kernel<<<nScanBlocks, SCAN_B>>>(N);
    scan_apply_kernel<<<nScanBlocks, SCAN_B>>>(N, 2 * E);

    fill_kernel<<<(nEdge2 + 255) / 256, 256>>>(u_idx, i_idx, E, NU);

    {
        size_t threads_total = (size_t)N * 32;
        int blocks = (int)((threads_total + 255) / 256);
        pull1_kernel<<<blocks, 256>>>(u_emb, i_emb, N, NU);
        pull2_kernel<<<blocks, 256>>>(u_emb, i_emb, out, N, NU);
    }
}

// round 16
// speedup vs baseline: 1.2035x; 1.1464x over previous
#include <cuda_runtime.h>
#include <cuda_fp16.h>
#include <cstdint>

// LightGCN 2-hop smoothing, pull-based SpMM over an on-the-fly CSR.
// x1 stored ONLY in fp16 (halves pass-2 gather bytes AND shrinks the L2
// working set to ~88MB << 126MB L2). fp32 accumulation everywhere.
// Loop shape = R8's verified branch-free clamped 8-slot form.
// out = (2*x0 + 2*x1 + x2)/3, x1 = S x0, x2 = S x1, S = D^-1/2 A D^-1/2.

#define EMB 64
#define MAX_NODES 200000
#define MAX_DEDGES 2500000
#define SCAN_B 256
#define MAX_SCAN_BLOCKS 1024

#define FULLMASK 0xffffffffu

__device__ int   g_deg[MAX_NODES];
__device__ float g_dis[MAX_NODES];
__device__ int   g_row[MAX_NODES + 1];
__device__ int   g_cursor[MAX_NODES];
__device__ int   g_bsums[MAX_SCAN_BLOCKS];
__device__ int   g_adj[MAX_DEDGES];
__device__ uint2 g_x1h[(size_t)MAX_NODES * 16];   // fp16 x1: 16 x uint2 (4 halves) per row

__device__ __forceinline__ unsigned h2_bits(__half2 h) {
    return *reinterpret_cast<unsigned*>(&h);
}
__device__ __forceinline__ __half2 bits_h2(unsigned u) {
    return *reinterpret_cast<__half2*>(&u);
}

__global__ void zero_deg_kernel(int N) {
    int n = blockIdx.x * blockDim.x + threadIdx.x;
    if (n < N) g_deg[n] = 0;
}

__global__ void deg_kernel(const int* __restrict__ u_idx,
                           const int* __restrict__ i_idx,
                           int E, int NU) {
    int e4 = blockIdx.x * blockDim.x + threadIdx.x;
    int base = e4 * 4;
    if (base + 3 < E) {
        int4 u = ((const int4*)u_idx)[e4];
        int4 i = ((const int4*)i_idx)[e4];
        atomicAdd(&g_deg[u.x], 1);
        atomicAdd(&g_deg[u.y], 1);
        atomicAdd(&g_deg[u.z], 1);
        atomicAdd(&g_deg[u.w], 1);
        atomicAdd(&g_deg[NU + i.x], 1);
        atomicAdd(&g_deg[NU + i.y], 1);
        atomicAdd(&g_deg[NU + i.z], 1);
        atomicAdd(&g_deg[NU + i.w], 1);
    } else {
        for (int e = base; e < E; e++) {
            atomicAdd(&g_deg[u_idx[e]], 1);
            atomicAdd(&g_deg[NU + i_idx[e]], 1);
        }
    }
}

__global__ void scan1_kernel(int N) {
    __shared__ int warp_tot[SCAN_B / 32];
    int t = threadIdx.x;
    int lane = t & 31;
    int wid = t >> 5;
    int idx = blockIdx.x * SCAN_B + t;
    int v = (idx < N) ? g_deg[idx] : 0;
    if (idx < N) g_dis[idx] = (v > 0) ? rsqrtf((float)v) : 0.0f;

    int s = v;
    #pragma unroll
    for (int off = 1; off < 32; off <<= 1) {
        int n = __shfl_up_sync(FULLMASK, s, off);
        if (lane >= off) s += n;
    }
    if (lane == 31) warp_tot[wid] = s;
    __syncthreads();
    if (wid == 0) {
        int w = (lane < SCAN_B / 32) ? warp_tot[lane] : 0;
        #pragma unroll
        for (int off = 1; off < 32; off <<= 1) {
            int n = __shfl_up_sync(FULLMASK, w, off);
            if (lane >= off) w += n;
        }
        if (lane < SCAN_B / 32) warp_tot[lane] = w;
    }
    __syncthreads();
    int base = (wid > 0) ? warp_tot[wid - 1] : 0;
    int incl = base + s;
    if (idx < N) g_row[idx] = incl - v;
    if (t == SCAN_B - 1) g_bsums[blockIdx.x] = incl;
}

__global__ void scan_apply_kernel(int N, int twoE) {
    __shared__ int red[SCAN_B / 32];
    int t = threadIdx.x;
    int lane = t & 31;
    int wid = t >> 5;

    int sum = 0;
    for (int j = t; j < blockIdx.x; j += SCAN_B) sum += g_bsums[j];
    #pragma unroll
    for (int off = 16; off > 0; off >>= 1)
        sum += __shfl_xor_sync(FULLMASK, sum, off);
    if (lane == 0) red[wid] = sum;
    __syncthreads();
    if (wid == 0) {
        int w = (lane < SCAN_B / 32) ? red[lane] : 0;
        #pragma unroll
        for (int off = 16; off > 0; off >>= 1)
            w += __shfl_xor_sync(FULLMASK, w, off);
        if (lane == 0) red[0] = w;
    }
    __syncthreads();
    int offset = red[0];

    int idx = blockIdx.x * SCAN_B + t;
    if (idx < N) {
        int r = g_row[idx] + offset;
        g_row[idx] = r;
        g_cursor[idx] = r;
    }
    if (idx == 0) g_row[N] = twoE;
}

__global__ void fill_kernel(const int* __restrict__ u_idx,
                            const int* __restrict__ i_idx,
                            int E, int NU) {
    int e4 = blockIdx.x * blockDim.x + threadIdx.x;
    int base = e4 * 4;
    if (base + 3 < E) {
        int4 u = ((const int4*)u_idx)[e4];
        int4 i = ((const int4*)i_idx)[e4];
        int gx = NU + i.x, gy = NU + i.y, gz = NU + i.z, gw = NU + i.w;
        g_adj[atomicAdd(&g_cursor[gx], 1)] = u.x;
        g_adj[atomicAdd(&g_cursor[gy], 1)] = u.y;
        g_adj[atomicAdd(&g_cursor[gz], 1)] = u.z;
        g_adj[atomicAdd(&g_cursor[gw], 1)] = u.w;
        g_adj[atomicAdd(&g_cursor[u.x], 1)] = gx;
        g_adj[atomicAdd(&g_cursor[u.y], 1)] = gy;
        g_adj[atomicAdd(&g_cursor[u.z], 1)] = gz;
        g_adj[atomicAdd(&g_cursor[u.w], 1)] = gw;
    } else {
        for (int e = base; e < E; e++) {
            int u = u_idx[e];
            int g = NU + i_idx[e];
            g_adj[atomicAdd(&g_cursor[g], 1)] = u;
            g_adj[atomicAdd(&g_cursor[u], 1)] = g;
        }
    }
}

// ---- pull pass 1: x1 = S x0, result stored in fp16 ----
__global__ void pull1_kernel(const float* __restrict__ u_emb,
                             const float* __restrict__ i_emb,
                             int N, int NU) {
    int warp = (int)(((size_t)blockIdx.x * blockDim.x + threadIdx.x) >> 5);
    int lane = threadIdx.x & 31;
    if (warp >= N) return;

    int half = lane >> 4;
    int q    = lane & 15;

    int start = g_row[warp];
    int end   = g_row[warp + 1];

    float4 acc = make_float4(0.f, 0.f, 0.f, 0.f);

    for (int k = start; k < end; k += 8) {
        int i0 = k + half, i1 = k + 2 + half, i2 = k + 4 + half, i3 = k + 6 + half;
        int lim = end - 1;
        int s0 = g_adj[min(i0, lim)];
        int s1 = g_adj[min(i1, lim)];
        int s2 = g_adj[min(i2, lim)];
        int s3 = g_adj[min(i3, lim)];
        float w0 = (i0 < end) ? g_dis[s0] : 0.f;
        float w1 = (i1 < end) ? g_dis[s1] : 0.f;
        float w2 = (i2 < end) ? g_dis[s2] : 0.f;
        float w3 = (i3 < end) ? g_dis[s3] : 0.f;
        const float4* p0 = (s0 < NU) ? (const float4*)(u_emb + (size_t)s0 * EMB)
                                     : (const float4*)(i_emb + (size_t)(s0 - NU) * EMB);
        const float4* p1 = (s1 < NU) ? (const float4*)(u_emb + (size_t)s1 * EMB)
                                     : (const float4*)(i_emb + (size_t)(s1 - NU) * EMB);
        const float4* p2 = (s2 < NU) ? (const float4*)(u_emb + (size_t)s2 * EMB)
                                     : (const float4*)(i_emb + (size_t)(s2 - NU) * EMB);
        const float4* p3 = (s3 < NU) ? (const float4*)(u_emb + (size_t)s3 * EMB)
                                     : (const float4*)(i_emb + (size_t)(s3 - NU) * EMB);
        float4 v0 = p0[q], v1 = p1[q], v2 = p2[q], v3 = p3[q];
        acc.x += w0 * v0.x + w1 * v1.x + w2 * v2.x + w3 * v3.x;
        acc.y += w0 * v0.y + w1 * v1.y + w2 * v2.y + w3 * v3.y;
        acc.z += w0 * v0.z + w1 * v1.z + w2 * v2.z + w3 * v3.z;
        acc.w += w0 * v0.w + w1 * v1.w + w2 * v2.w + w3 * v3.w;
    }

    acc.x += __shfl_xor_sync(FULLMASK, acc.x, 16);
    acc.y += __shfl_xor_sync(FULLMASK, acc.y, 16);
    acc.z += __shfl_xor_sync(FULLMASK, acc.z, 16);
    acc.w += __shfl_xor_sync(FULLMASK, acc.w, 16);

    if (half == 0) {
        float dn = g_dis[warp];
        __half2 h0 = __floats2half2_rn(dn * acc.x, dn * acc.y);
        __half2 h1 = __floats2half2_rn(dn * acc.z, dn * acc.w);
        uint2 v;
        v.x = h2_bits(h0);
        v.y = h2_bits(h1);
        g_x1h[(size_t)warp * 16 + q] = v;
    }
}

__device__ __forceinline__ float4 unpack_h4(uint2 v) {
    float2 f0 = __half22float2(bits_h2(v.x));
    float2 f1 = __half22float2(bits_h2(v.y));
    return make_float4(f0.x, f0.y, f1.x, f1.y);
}

// ---- pull pass 2 fused with output combine ----
// out[n] = (2*x0[n] + 2*x1[n] + dis[n]*sum dis[s]*x1[s]) / 3  (x1 from fp16)
__global__ void pull2_kernel(const float* __restrict__ u_emb,
                             const float* __restrict__ i_emb,
                             float* __restrict__ out,
                             int N, int NU) {
    int warp = (int)(((size_t)blockIdx.x * blockDim.x + threadIdx.x) >> 5);
    int lane = threadIdx.x & 31;
    if (warp >= N) return;

    int half = lane >> 4;
    int q    = lane & 15;

    int start = g_row[warp];
    int end   = g_row[warp + 1];

    float4 acc = make_float4(0.f, 0.f, 0.f, 0.f);

    for (int k = start; k < end; k += 8) {
        int i0 = k + half, i1 = k + 2 + half, i2 = k + 4 + half, i3 = k + 6 + half;
        int lim = end - 1;
        int s0 = g_adj[min(i0, lim)];
        int s1 = g_adj[min(i1, lim)];
        int s2 = g_adj[min(i2, lim)];
        int s3 = g_adj[min(i3, lim)];
        float w0 = (i0 < end) ? g_dis[s0] : 0.f;
        float w1 = (i1 < end) ? g_dis[s1] : 0.f;
        float w2 = (i2 < end) ? g_dis[s2] : 0.f;
        float w3 = (i3 < end) ? g_dis[s3] : 0.f;
        float4 v0 = unpack_h4(g_x1h[(size_t)s0 * 16 + q]);
        float4 v1 = unpack_h4(g_x1h[(size_t)s1 * 16 + q]);
        float4 v2 = unpack_h4(g_x1h[(size_t)s2 * 16 + q]);
        float4 v3 = unpack_h4(g_x1h[(size_t)s3 * 16 + q]);
        acc.x += w0 * v0.x + w1 * v1.x + w2 * v2.x + w3 * v3.x;
        acc.y += w0 * v0.y + w1 * v1.y + w2 * v2.y + w3 * v3.y;
        acc.z += w0 * v0.z + w1 * v1.z + w2 * v2.z + w3 * v3.z;
        acc.w += w0 * v0.w + w1 * v1.w + w2 * v2.w + w3 * v3.w;
    }

    acc.x += __shfl_xor_sync(FULLMASK, acc.x, 16);
    acc.y += __shfl_xor_sync(FULLMASK, acc.y, 16);
    acc.z += __shfl_xor_sync(FULLMASK, acc.z, 16);
    acc.w += __shfl_xor_sync(FULLMASK, acc.w, 16);

    if (half == 0) {
        float dn = g_dis[warp];
        const float4* x0b = (warp < NU)
            ? (const float4*)(u_emb + (size_t)warp * EMB)
            : (const float4*)(i_emb + (size_t)(warp - NU) * EMB);
        float4 x0v = x0b[q];
        float4 x1v = unpack_h4(g_x1h[(size_t)warp * 16 + q]);
        const float inv3 = 1.0f / 3.0f;
        float4 o;
        o.x = (2.0f * x0v.x + 2.0f * x1v.x + dn * acc.x) * inv3;
        o.y = (2.0f * x0v.y + 2.0f * x1v.y + dn * acc.y) * inv3;
        o.z = (2.0f * x0v.z + 2.0f * x1v.z + dn * acc.z) * inv3;
        o.w = (2.0f * x0v.w + 2.0f * x1v.w + dn * acc.w) * inv3;
        ((float4*)(out + (size_t)warp * EMB))[q] = o;
    }
}

extern "C" void kernel_launch(void* const* d_in, const int* in_sizes, int n_in,
                              void* d_out, int out_size) {
    const float* u_emb = (const float*)d_in[0];
    const float* i_emb = (const float*)d_in[1];
    const int*   u_idx = (const int*)d_in[2];
    const int*   i_idx = (const int*)d_in[3];
    float*       out   = (float*)d_out;

    int NU = in_sizes[0] / EMB;
    int NI = in_sizes[1] / EMB;
    int E  = in_sizes[2];
    int N  = NU + NI;

    int nScanBlocks = (N + SCAN_B - 1) / SCAN_B;
    int nEdge4 = (E + 3) / 4;

    zero_deg_kernel<<<(N + 255) / 256, 256>>>(N);
    deg_kernel<<<(nEdge4 + 255) / 256, 256>>>(u_idx, i_idx, E, NU);

    scan1_kernel<<<nScanBlocks, SCAN_B>>>(N);
    scan_apply_kernel<<<nScanBlocks, SCAN_B>>>(N, 2 * E);

    fill_kernel<<<(nEdge4 + 255) / 256, 256>>>(u_idx, i_idx, E, NU);

    {
        size_t threads_total = (size_t)N * 32;
        int blocks = (int)((threads_total + 255) / 256);
        pull1_kernel<<<blocks, 256>>>(u_emb, i_emb, N, NU);
        pull2_kernel<<<blocks, 256>>>(u_emb, i_emb, out, N, NU);
    }
}